// round 16
// baseline (speedup 1.0000x reference)
#include <cuda_runtime.h>
#include <math.h>

#define MDIM 8192
#define NDIM 8192
#define KDIM 256
#define BM 64
#define BN 64
#define BK 16
#define LDAS 68          // padded smem leading dim (keeps 16B alignment, mild bank spread)
#define NBINS 4096       // 12-bit float-key histogram
#define CAP 65536
#define TOPK 256

// ---------------- device scratch (static globals: no runtime allocation) ----------------
__device__ float g_E[(size_t)MDIM * (size_t)NDIM];            // 256MB: exp(2*s - 2)
__device__ float g_rowPart[(NDIM / BN) * MDIM];               // per-column-tile partial row sums
__device__ float g_colPart[(MDIM / BM) * NDIM];               // per-row-tile partial col sums
__device__ float g_rowsum[MDIM];
__device__ float g_colsum[NDIM];
__device__ unsigned int g_hist[NBINS];
__device__ unsigned int g_thresh;
__device__ unsigned int g_cnt;
__device__ unsigned long long g_cand[CAP];

// ---------------- packed fp32x2 helpers (Blackwell FFMA2) ----------------
__device__ __forceinline__ unsigned long long pack2(float lo, float hi) {
    unsigned long long r;
    asm("mov.b64 %0, {%1, %2};" : "=l"(r) : "f"(lo), "f"(hi));
    return r;
}
__device__ __forceinline__ unsigned long long ffma2(unsigned long long a,
                                                    unsigned long long b,
                                                    unsigned long long c) {
    unsigned long long d;
    asm("fma.rn.f32x2 %0, %1, %2, %3;" : "=l"(d) : "l"(a), "l"(b), "l"(c));
    return d;
}
__device__ __forceinline__ void unpack2(unsigned long long v, float& lo, float& hi) {
    asm("mov.b64 {%0, %1}, %2;" : "=f"(lo), "=f"(hi) : "l"(v));
}

// ---------------- init: zero histogram + candidate counter ----------------
__global__ void init_kernel() {
    int i = blockIdx.x * blockDim.x + threadIdx.x;
    if (i < NBINS) g_hist[i] = 0u;
    if (i == NBINS) g_cnt = 0u;
}

// ---------------- GEMM + exp + deterministic partial row/col sums ----------------
// 64x64 tile per 256-thread block; each thread owns a 4x4 microtile using fma.rn.f32x2.
__global__ void __launch_bounds__(256) gemm_kernel(const float* __restrict__ A,
                                                   const float* __restrict__ B) {
    __shared__ float As[BK][LDAS];   // [k][m]
    __shared__ float Bs[BK][LDAS];   // [k][n]
    __shared__ float red[BM][17];

    const int tid = threadIdx.x;
    const int tx = tid & 15;    // m group (4 rows)
    const int ty = tid >> 4;    // n group (4 cols)
    const int m0 = blockIdx.y * BM;
    const int n0 = blockIdx.x * BN;

    const int lr = tid >> 2;          // 0..63: tile row for smem fill
    const int lk = (tid & 3) * 4;     // 0,4,8,12: k offset for smem fill

    unsigned long long acc[4][2];
#pragma unroll
    for (int i = 0; i < 4; i++) { acc[i][0] = 0ULL; acc[i][1] = 0ULL; }

    const float* Arow = A + (size_t)(m0 + lr) * KDIM;
    const float* Brow = B + (size_t)(n0 + lr) * KDIM;

    for (int k0 = 0; k0 < KDIM; k0 += BK) {
        float4 av = *(const float4*)(Arow + k0 + lk);
        float4 bv = *(const float4*)(Brow + k0 + lk);
        __syncthreads();
        As[lk + 0][lr] = av.x; As[lk + 1][lr] = av.y;
        As[lk + 2][lr] = av.z; As[lk + 3][lr] = av.w;
        Bs[lk + 0][lr] = bv.x; Bs[lk + 1][lr] = bv.y;
        Bs[lk + 2][lr] = bv.z; Bs[lk + 3][lr] = bv.w;
        __syncthreads();
#pragma unroll
        for (int k = 0; k < BK; k++) {
            float4 a = *(const float4*)&As[k][tx * 4];
            float4 b = *(const float4*)&Bs[k][ty * 4];
            unsigned long long b01 = pack2(b.x, b.y);
            unsigned long long b23 = pack2(b.z, b.w);
            float aa[4] = {a.x, a.y, a.z, a.w};
#pragma unroll
            for (int i = 0; i < 4; i++) {
                unsigned long long ap = pack2(aa[i], aa[i]);
                acc[i][0] = ffma2(ap, b01, acc[i][0]);
                acc[i][1] = ffma2(ap, b23, acc[i][1]);
            }
        }
    }

    // epilogue: e = exp(2s - 2); store E; deterministic partial sums
    float e[4][4];
    float rsum[4];
#pragma unroll
    for (int i = 0; i < 4; i++) {
        float s0, s1, s2, s3;
        unpack2(acc[i][0], s0, s1);
        unpack2(acc[i][1], s2, s3);
        e[i][0] = expf(fmaf(2.0f, s0, -2.0f));
        e[i][1] = expf(fmaf(2.0f, s1, -2.0f));
        e[i][2] = expf(fmaf(2.0f, s2, -2.0f));
        e[i][3] = expf(fmaf(2.0f, s3, -2.0f));
        int row = m0 + tx * 4 + i;
        float4 ev = make_float4(e[i][0], e[i][1], e[i][2], e[i][3]);
        *(float4*)&g_E[(size_t)row * NDIM + (n0 + ty * 4)] = ev;
        rsum[i] = ((e[i][0] + e[i][1]) + e[i][2]) + e[i][3];
    }

    // row sums for this block's 64 rows (fixed order -> deterministic)
#pragma unroll
    for (int i = 0; i < 4; i++) red[tx * 4 + i][ty] = rsum[i];
    __syncthreads();
    if (tid < BM) {
        float s = 0.f;
#pragma unroll
        for (int j = 0; j < 16; j++) s += red[tid][j];
        g_rowPart[blockIdx.x * MDIM + m0 + tid] = s;
    }
    __syncthreads();
    // col sums
#pragma unroll
    for (int j = 0; j < 4; j++) {
        float c = ((e[0][j] + e[1][j]) + e[2][j]) + e[3][j];
        red[ty * 4 + j][tx] = c;
    }
    __syncthreads();
    if (tid < BN) {
        float s = 0.f;
#pragma unroll
        for (int j = 0; j < 16; j++) s += red[tid][j];
        g_colPart[blockIdx.y * NDIM + n0 + tid] = s;
    }
}

// ---------------- final row/col sum reduction (deterministic fixed order) ----------------
__global__ void reduce_sums_kernel() {
    int i = blockIdx.x * blockDim.x + threadIdx.x;
    if (i < MDIM) {
        float s = 0.f;
        for (int j = 0; j < NDIM / BN; j++) s += g_rowPart[j * MDIM + i];
        g_rowsum[i] = s;
    } else if (i < MDIM + NDIM) {
        int n = i - MDIM;
        float s = 0.f;
        for (int j = 0; j < MDIM / BM; j++) s += g_colPart[j * NDIM + n];
        g_colsum[n] = s;
    }
}

// score exactly as the reference: (e/rowsum) * (e/colsum), IEEE divides
__device__ __forceinline__ void compute_scores(size_t base, float sc[4]) {
    int m = (int)(base >> 13);
    int n = (int)(base & 8191);
    float4 ev = *(const float4*)&g_E[base];
    float R = g_rowsum[m];
    float4 C = *(const float4*)&g_colsum[n];
    sc[0] = (ev.x / R) * (ev.x / C.x);
    sc[1] = (ev.y / R) * (ev.y / C.y);
    sc[2] = (ev.z / R) * (ev.z / C.z);
    sc[3] = (ev.w / R) * (ev.w / C.w);
}

// ---------------- pass: 12-bit histogram of score float bits ----------------
__global__ void __launch_bounds__(256) hist_kernel() {
    __shared__ unsigned int h[NBINS];
    for (int i = threadIdx.x; i < NBINS; i += 256) h[i] = 0u;
    __syncthreads();

    int gid = blockIdx.x * 256 + threadIdx.x;
    size_t base = (size_t)gid * 4;
    float sc[4];
    compute_scores(base, sc);

    unsigned lane = threadIdx.x & 31u;
#pragma unroll
    for (int j = 0; j < 4; j++) {
        unsigned b = __float_as_uint(sc[j]) >> 20;   // 12-bit bucket (scores > 0)
        unsigned mask = __match_any_sync(0xffffffffu, b);
        if ((int)lane == (__ffs(mask) - 1)) atomicAdd(&h[b], (unsigned)__popc(mask));
    }
    __syncthreads();
    for (int i = threadIdx.x; i < NBINS; i += 256) {
        unsigned v = h[i];
        if (v) atomicAdd(&g_hist[i], v);
    }
}

// ---------------- pass: find threshold bucket (count(bucket >= B*) >= 256) ----------------
__global__ void __launch_bounds__(1024) scan_kernel() {
    __shared__ unsigned int h[NBINS];
    for (int i = threadIdx.x; i < NBINS; i += blockDim.x) h[i] = g_hist[i];
    __syncthreads();
    if (threadIdx.x == 0) {
        unsigned cum = 0;
        int b = NBINS - 1;
        for (; b >= 0; b--) {
            cum += h[b];
            if (cum >= TOPK) break;
        }
        if (b < 0) b = 0;
        g_thresh = (unsigned)b;
    }
}

// ---------------- pass: collect candidates >= threshold bucket ----------------
__global__ void __launch_bounds__(256) collect_kernel() {
    int gid = blockIdx.x * 256 + threadIdx.x;
    size_t base = (size_t)gid * 4;
    float sc[4];
    compute_scores(base, sc);
    unsigned th = g_thresh;
#pragma unroll
    for (int j = 0; j < 4; j++) {
        unsigned bits = __float_as_uint(sc[j]);
        if ((bits >> 20) >= th) {
            unsigned pos = atomicAdd(&g_cnt, 1u);
            if (pos < CAP) {
                // key: score desc primary, flat index asc secondary (matches lax.top_k ties)
                unsigned flat = (unsigned)(base + j);
                g_cand[pos] = ((unsigned long long)bits << 32) |
                              (unsigned long long)(0xFFFFFFFFu - flat);
            }
        }
    }
}

// ---------------- pass: select top-256 by iterative parallel argmax ----------------
__global__ void __launch_bounds__(1024) topk_kernel(float* __restrict__ out) {
    __shared__ unsigned long long wkey[32];
    __shared__ int wpos[32];
    __shared__ unsigned long long sel[TOPK];

    int tid = threadIdx.x;
    int lane = tid & 31;
    int wid = tid >> 5;
    unsigned cnt = g_cnt;
    int n = cnt < CAP ? (int)cnt : CAP;

    for (int it = 0; it < TOPK; it++) {
        unsigned long long best = 0ULL;
        int bpos = -1;
        for (int i = tid; i < n; i += 1024) {
            unsigned long long v = g_cand[i];
            if (v > best) { best = v; bpos = i; }
        }
#pragma unroll
        for (int off = 16; off > 0; off >>= 1) {
            unsigned long long ok = __shfl_down_sync(0xffffffffu, best, off);
            int op = __shfl_down_sync(0xffffffffu, bpos, off);
            if (ok > best) { best = ok; bpos = op; }
        }
        if (lane == 0) { wkey[wid] = best; wpos[wid] = bpos; }
        __syncthreads();
        if (wid == 0) {
            best = wkey[lane];
            bpos = wpos[lane];
#pragma unroll
            for (int off = 16; off > 0; off >>= 1) {
                unsigned long long ok = __shfl_down_sync(0xffffffffu, best, off);
                int op = __shfl_down_sync(0xffffffffu, bpos, off);
                if (ok > best) { best = ok; bpos = op; }
            }
            if (lane == 0) {
                sel[it] = best;
                if (bpos >= 0) g_cand[bpos] = 0ULL;   // remove winner
            }
        }
        __syncthreads();
    }

    if (tid < TOPK) {
        unsigned long long k = sel[tid];
        unsigned bits = (unsigned)(k >> 32);
        unsigned flat = 0xFFFFFFFFu - (unsigned)(k & 0xFFFFFFFFULL);
        out[tid]            = (float)(flat >> 13);     // ref index = flat / 8192
        out[TOPK + tid]     = (float)(flat & 8191u);   // src index = flat % 8192
        out[2 * TOPK + tid] = __uint_as_float(bits);   // score
    }
}

// ---------------- launch ----------------
extern "C" void kernel_launch(void* const* d_in, const int* in_sizes, int n_in,
                              void* d_out, int out_size) {
    const float* ref = (const float*)d_in[0];
    const float* src = (const float*)d_in[1];
    float* out = (float*)d_out;

    init_kernel<<<17, 256>>>();                            // zero hist + counter

    dim3 gg(NDIM / BN, MDIM / BM);                         // 128 x 128
    gemm_kernel<<<gg, 256>>>(ref, src);

    reduce_sums_kernel<<<(MDIM + NDIM) / 256, 256>>>();

    int nvec_blocks = (int)(((size_t)MDIM * NDIM / 4) / 256);  // 65536
    hist_kernel<<<nvec_blocks, 256>>>();
    scan_kernel<<<1, 1024>>>();
    collect_kernel<<<nvec_blocks, 256>>>();
    topk_kernel<<<1, 1024>>>(out);
}

// round 17
// speedup vs baseline: 1.3090x; 1.3090x over previous
#include <cuda_runtime.h>
#include <math.h>

#define MDIM 8192
#define NDIM 8192
#define KDIM 256
#define BM 128
#define BN 128
#define BK 16
#define NTILE (NDIM / BN)     // 64
#define MTILE (MDIM / BM)     // 64
#define NBINS 4096            // 12-bit key: sign(0)+8exp+4mant of sqrt(score)
#define KSHIFT 19
#define CAP 262144
#define SORT_MAX 16384
#define TOPK 256
#define HBLOCKS 2048

// ---------------- device scratch ----------------
__device__ float g_E[(size_t)MDIM * (size_t)NDIM];     // 256MB: exp(2*s - 2)
__device__ float g_rowPart[NTILE * MDIM];
__device__ float g_colPart[MTILE * NDIM];
__device__ float g_rowsum[MDIM];
__device__ float g_colsum[NDIM];
__device__ float g_invRh[MDIM];                        // rsqrt(rowsum)
__device__ float g_invCh[NDIM];                        // rsqrt(colsum)
__device__ unsigned int g_hist[NBINS];
__device__ unsigned int g_thresh;
__device__ unsigned int g_cnt;
__device__ unsigned long long g_cand[CAP];

// ---------------- packed fp32x2 helpers ----------------
__device__ __forceinline__ unsigned long long pack2(float lo, float hi) {
    unsigned long long r;
    asm("mov.b64 %0, {%1, %2};" : "=l"(r) : "f"(lo), "f"(hi));
    return r;
}
__device__ __forceinline__ unsigned long long ffma2(unsigned long long a,
                                                    unsigned long long b,
                                                    unsigned long long c) {
    unsigned long long d;
    asm("fma.rn.f32x2 %0, %1, %2, %3;" : "=l"(d) : "l"(a), "l"(b), "l"(c));
    return d;
}
__device__ __forceinline__ void unpack2(unsigned long long v, float& lo, float& hi) {
    asm("mov.b64 {%0, %1}, %2;" : "=f"(lo), "=f"(hi) : "l"(v));
}

// ---------------- init ----------------
__global__ void init_kernel() {
    int i = blockIdx.x * blockDim.x + threadIdx.x;
    if (i < NBINS) g_hist[i] = 0u;
    if (i == NBINS) g_cnt = 0u;
}

// ---------------- GEMM 128x128 tile, 8x8 microtile, FFMA2 ----------------
__global__ void __launch_bounds__(256, 2) gemm_kernel(const float* __restrict__ A,
                                                      const float* __restrict__ B) {
    __shared__ float As[BK][BM + 4];   // 16 x 132 (16B-aligned rows)
    __shared__ float Bs[BK][BN + 4];

    const int tid = threadIdx.x;
    const int tx = tid & 15;          // m group (8 rows)
    const int ty = tid >> 4;          // n group (8 cols)
    const int m0 = blockIdx.y * BM;
    const int n0 = blockIdx.x * BN;

    const int lr = tid >> 1;          // 0..127: tile row for smem fill
    const int lk = (tid & 1) * 8;     // 0 or 8: k offset for smem fill

    unsigned long long acc[8][4];
#pragma unroll
    for (int i = 0; i < 8; i++)
#pragma unroll
        for (int j = 0; j < 4; j++) acc[i][j] = 0ULL;

    const float* Arow = A + (size_t)(m0 + lr) * KDIM + lk;
    const float* Brow = B + (size_t)(n0 + lr) * KDIM + lk;

    for (int k0 = 0; k0 < KDIM; k0 += BK) {
        float4 a0 = *(const float4*)(Arow + k0);
        float4 a1 = *(const float4*)(Arow + k0 + 4);
        float4 b0 = *(const float4*)(Brow + k0);
        float4 b1 = *(const float4*)(Brow + k0 + 4);
        __syncthreads();
        As[lk + 0][lr] = a0.x; As[lk + 1][lr] = a0.y;
        As[lk + 2][lr] = a0.z; As[lk + 3][lr] = a0.w;
        As[lk + 4][lr] = a1.x; As[lk + 5][lr] = a1.y;
        As[lk + 6][lr] = a1.z; As[lk + 7][lr] = a1.w;
        Bs[lk + 0][lr] = b0.x; Bs[lk + 1][lr] = b0.y;
        Bs[lk + 2][lr] = b0.z; Bs[lk + 3][lr] = b0.w;
        Bs[lk + 4][lr] = b1.x; Bs[lk + 5][lr] = b1.y;
        Bs[lk + 6][lr] = b1.z; Bs[lk + 7][lr] = b1.w;
        __syncthreads();
#pragma unroll
        for (int k = 0; k < BK; k++) {
            float4 av0 = *(const float4*)&As[k][tx * 8];
            float4 av1 = *(const float4*)&As[k][tx * 8 + 4];
            ulonglong2 bv0 = *(const ulonglong2*)&Bs[k][ty * 8];       // pre-packed pairs
            ulonglong2 bv1 = *(const ulonglong2*)&Bs[k][ty * 8 + 4];
            unsigned long long b2[4] = {bv0.x, bv0.y, bv1.x, bv1.y};
            float a[8] = {av0.x, av0.y, av0.z, av0.w, av1.x, av1.y, av1.z, av1.w};
#pragma unroll
            for (int i = 0; i < 8; i++) {
                unsigned long long ap = pack2(a[i], a[i]);
                acc[i][0] = ffma2(ap, b2[0], acc[i][0]);
                acc[i][1] = ffma2(ap, b2[1], acc[i][1]);
                acc[i][2] = ffma2(ap, b2[2], acc[i][2]);
                acc[i][3] = ffma2(ap, b2[3], acc[i][3]);
            }
        }
    }

    // ---- epilogue: exp, store E, deterministic partial row/col sums ----
    __syncthreads();                       // all smem reads done -> reuse As/Bs
    float* redR = &As[0][0];               // [row 0..127][ty 0..15], stride 16
    float* redC = &Bs[0][0];               // [col 0..127][tx 0..15], stride 16

    float csum[8];
#pragma unroll
    for (int j = 0; j < 8; j++) csum[j] = 0.f;

#pragma unroll
    for (int i = 0; i < 8; i++) {
        float v[8];
        unpack2(acc[i][0], v[0], v[1]);
        unpack2(acc[i][1], v[2], v[3]);
        unpack2(acc[i][2], v[4], v[5]);
        unpack2(acc[i][3], v[6], v[7]);
        float rsum = 0.f;
#pragma unroll
        for (int j = 0; j < 8; j++) {
            v[j] = expf(fmaf(2.0f, v[j], -2.0f));
            rsum += v[j];
            csum[j] += v[j];
        }
        int row = m0 + tx * 8 + i;
        float4 e0 = make_float4(v[0], v[1], v[2], v[3]);
        float4 e1 = make_float4(v[4], v[5], v[6], v[7]);
        size_t off = (size_t)row * NDIM + (n0 + ty * 8);
        *(float4*)&g_E[off] = e0;
        *(float4*)&g_E[off + 4] = e1;
        redR[(tx * 8 + i) * 16 + ty] = rsum;
    }
#pragma unroll
    for (int j = 0; j < 8; j++) redC[(ty * 8 + j) * 16 + tx] = csum[j];
    __syncthreads();

    if (tid < BM) {
        float s = 0.f;
#pragma unroll
        for (int j = 0; j < 16; j++) s += redR[tid * 16 + j];
        g_rowPart[blockIdx.x * MDIM + m0 + tid] = s;
    } else {
        int c = tid - 128;
        float s = 0.f;
#pragma unroll
        for (int j = 0; j < 16; j++) s += redC[c * 16 + j];
        g_colPart[blockIdx.y * NDIM + n0 + c] = s;
    }
}

// ---------------- final sums + rsqrt factors ----------------
__global__ void reduce_sums_kernel() {
    int i = blockIdx.x * blockDim.x + threadIdx.x;
    if (i < MDIM) {
        float s = 0.f;
        for (int j = 0; j < NTILE; j++) s += g_rowPart[j * MDIM + i];
        g_rowsum[i] = s;
        g_invRh[i] = rsqrtf(s);
    } else if (i < MDIM + NDIM) {
        int n = i - MDIM;
        float s = 0.f;
        for (int j = 0; j < MTILE; j++) s += g_colPart[j * NDIM + n];
        g_colsum[n] = s;
        g_invCh[n] = rsqrtf(s);
    }
}

// ---------------- pass 1: histogram of sqrt-score keys (grid-stride) ----------------
__global__ void __launch_bounds__(256) hist_kernel() {
    __shared__ unsigned int h[NBINS];
    for (int i = threadIdx.x; i < NBINS; i += 256) h[i] = 0u;
    __syncthreads();

    const size_t total = (size_t)MDIM * NDIM / 4;
    unsigned lane = threadIdx.x & 31u;
    for (size_t v = (size_t)blockIdx.x * 256 + threadIdx.x; v < total;
         v += (size_t)HBLOCKS * 256) {
        size_t base = v * 4;
        int m = (int)(base >> 13);
        int n = (int)(base & 8191);
        float4 ev = *(const float4*)&g_E[base];
        float ir = g_invRh[m];
        float4 ic = *(const float4*)&g_invCh[n];
        float k0 = ev.x * (ir * ic.x);
        float k1 = ev.y * (ir * ic.y);
        float k2 = ev.z * (ir * ic.z);
        float k3 = ev.w * (ir * ic.w);
        unsigned bb[4] = {__float_as_uint(k0) >> KSHIFT, __float_as_uint(k1) >> KSHIFT,
                          __float_as_uint(k2) >> KSHIFT, __float_as_uint(k3) >> KSHIFT};
#pragma unroll
        for (int j = 0; j < 4; j++) {
            unsigned mask = __match_any_sync(0xffffffffu, bb[j]);
            if ((int)lane == (__ffs(mask) - 1)) atomicAdd(&h[bb[j]], (unsigned)__popc(mask));
        }
    }
    __syncthreads();
    for (int i = threadIdx.x; i < NBINS; i += 256) {
        unsigned v = h[i];
        if (v) atomicAdd(&g_hist[i], v);
    }
}

// ---------------- pass 2: threshold bucket (with 1-bucket safety margin) ----------------
__global__ void __launch_bounds__(1024) scan_kernel() {
    __shared__ unsigned int h[NBINS];
    for (int i = threadIdx.x; i < NBINS; i += blockDim.x) h[i] = g_hist[i];
    __syncthreads();
    if (threadIdx.x == 0) {
        unsigned cum = 0;
        int b = NBINS - 1;
        for (; b >= 0; b--) {
            cum += h[b];
            if (cum >= TOPK) break;
        }
        if (b < 1) b = 1;
        g_thresh = (unsigned)(b - 1);   // margin for rsqrt-key rounding
    }
}

// ---------------- pass 3: collect candidates, exact IEEE score per candidate ----------------
__global__ void __launch_bounds__(256) collect_kernel() {
    const size_t total = (size_t)MDIM * NDIM / 4;
    unsigned th = g_thresh;
    for (size_t v = (size_t)blockIdx.x * 256 + threadIdx.x; v < total;
         v += (size_t)HBLOCKS * 256) {
        size_t base = v * 4;
        int m = (int)(base >> 13);
        int n = (int)(base & 8191);
        float4 ev = *(const float4*)&g_E[base];
        float ir = g_invRh[m];
        float4 ic = *(const float4*)&g_invCh[n];
        float kk[4] = {ev.x * (ir * ic.x), ev.y * (ir * ic.y),
                       ev.z * (ir * ic.z), ev.w * (ir * ic.w)};
        float ee[4] = {ev.x, ev.y, ev.z, ev.w};
#pragma unroll
        for (int j = 0; j < 4; j++) {
            if ((__float_as_uint(kk[j]) >> KSHIFT) >= th) {
                float R = g_rowsum[m];
                float C = g_colsum[n + j];
                float sc = (ee[j] / R) * (ee[j] / C);   // exact reference expression
                unsigned pos = atomicAdd(&g_cnt, 1u);
                if (pos < CAP) {
                    unsigned flat = (unsigned)(base + j);
                    g_cand[pos] = ((unsigned long long)__float_as_uint(sc) << 32) |
                                  (unsigned long long)(0xFFFFFFFFu - flat);
                }
            }
        }
    }
}

// ---------------- pass 4: top-256 via in-smem bitonic sort ----------------
__global__ void __launch_bounds__(1024) topk_kernel(float* __restrict__ out) {
    extern __shared__ unsigned long long buf[];
    __shared__ unsigned long long wkey[32];
    __shared__ int wpos[32];

    int tid = threadIdx.x;
    unsigned cnt = g_cnt;
    int n = cnt < CAP ? (int)cnt : CAP;

    if (n <= SORT_MAX) {
        int np = 256;
        while (np < n) np <<= 1;
        for (int i = tid; i < np; i += 1024) buf[i] = (i < n) ? g_cand[i] : 0ULL;
        __syncthreads();
        for (int k = 2; k <= np; k <<= 1) {
            for (int j = k >> 1; j > 0; j >>= 1) {
                for (int i = tid; i < np; i += 1024) {
                    int ixj = i ^ j;
                    if (ixj > i) {
                        unsigned long long a = buf[i], b = buf[ixj];
                        bool desc = ((i & k) == 0);
                        if (desc ? (a < b) : (a > b)) { buf[i] = b; buf[ixj] = a; }
                    }
                }
                __syncthreads();
            }
        }
    } else {
        // fallback: iterative argmax over global (rare fat-bucket case)
        int lane = tid & 31, wid = tid >> 5;
        for (int it = 0; it < TOPK; it++) {
            unsigned long long best = 0ULL;
            int bpos = -1;
            for (int i = tid; i < n; i += 1024) {
                unsigned long long v = g_cand[i];
                if (v > best) { best = v; bpos = i; }
            }
#pragma unroll
            for (int off = 16; off > 0; off >>= 1) {
                unsigned long long ok = __shfl_down_sync(0xffffffffu, best, off);
                int op = __shfl_down_sync(0xffffffffu, bpos, off);
                if (ok > best) { best = ok; bpos = op; }
            }
            if (lane == 0) { wkey[wid] = best; wpos[wid] = bpos; }
            __syncthreads();
            if (wid == 0) {
                best = wkey[lane]; bpos = wpos[lane];
#pragma unroll
                for (int off = 16; off > 0; off >>= 1) {
                    unsigned long long ok = __shfl_down_sync(0xffffffffu, best, off);
                    int op = __shfl_down_sync(0xffffffffu, bpos, off);
                    if (ok > best) { best = ok; bpos = op; }
                }
                if (lane == 0) {
                    buf[it] = best;
                    if (bpos >= 0) g_cand[bpos] = 0ULL;
                }
            }
            __syncthreads();
        }
    }

    if (tid < TOPK) {
        unsigned long long k = buf[tid];
        unsigned bits = (unsigned)(k >> 32);
        unsigned flat = 0xFFFFFFFFu - (unsigned)(k & 0xFFFFFFFFULL);
        out[tid]            = (float)(flat >> 13);
        out[TOPK + tid]     = (float)(flat & 8191u);
        out[2 * TOPK + tid] = __uint_as_float(bits);
    }
}

// ---------------- launch ----------------
extern "C" void kernel_launch(void* const* d_in, const int* in_sizes, int n_in,
                              void* d_out, int out_size) {
    const float* ref = (const float*)d_in[0];
    const float* src = (const float*)d_in[1];
    float* out = (float*)d_out;

    cudaFuncSetAttribute(topk_kernel, cudaFuncAttributeMaxDynamicSharedMemorySize,
                         SORT_MAX * sizeof(unsigned long long));

    init_kernel<<<(NBINS + 256) / 256, 256>>>();

    dim3 gg(NDIM / BN, MDIM / BM);    // 64 x 64
    gemm_kernel<<<gg, 256>>>(ref, src);

    reduce_sums_kernel<<<(MDIM + NDIM) / 256, 256>>>();

    hist_kernel<<<HBLOCKS, 256>>>();
    scan_kernel<<<1, 1024>>>();
    collect_kernel<<<HBLOCKS, 256>>>();
    topk_kernel<<<1, 1024, SORT_MAX * sizeof(unsigned long long)>>>(out);
}